// round 2
// baseline (speedup 1.0000x reference)
#include <cuda_runtime.h>

// Problem constants
#define T_LEN   4096
#define D_DIM   512
#define N_DIM   16
#define TWO_N   32
#define DQ      128            // D/4 (float4 groups per row)
#define SEG     32             // number of segments (== warp size for scan)
#define L_SEG   128            // steps per segment (SEG*L_SEG == T_LEN)
#define CG      2048           // chain groups = N*D/4
#define NCHAIN  8192           // scalar chains = N*D
#define BIG_THREADS (SEG*CG)   // 65536

// Scratch (device globals: no allocation allowed). Logical layout: [SEG][NCHAIN] scalars.
__device__ float4 g_b  [SEG*CG];   // ha forcing per (seg, chain)
__device__ float4 g_f  [SEG*CG];   // hv forcing per (seg, chain)
__device__ float4 g_hab[SEG*CG];   // ha boundary at segment start
__device__ float4 g_hvb[SEG*CG];   // hv boundary at segment start

__device__ __forceinline__ float sqrt_approx(float v) {
    float r;
    asm("sqrt.approx.f32 %0, %1;" : "=f"(r) : "f"(v));
    return r;
}

// ---------------------------------------------------------------------------
// K1: zero-state ha replay per segment -> forcing term b
// ---------------------------------------------------------------------------
__global__ void k_b(const float4* __restrict__ x4, const float4* __restrict__ a4p) {
    int tid = blockIdx.x * blockDim.x + threadIdx.x;
    int s  = tid >> 11;          // segment
    int cg = tid & (CG - 1);     // chain group (n*128 + g)
    int g  = cg & (DQ - 1);

    float4 a = a4p[cg];
    float qx = 0.f, qy = 0.f, qz = 0.f, qw = 0.f;
    const float4* xp = x4 + (size_t)(s * L_SEG) * DQ + g;

    #pragma unroll 4
    for (int i = 0; i < L_SEG; i++) {
        float4 xv = xp[(size_t)i * DQ];
        qx = fmaf(a.x, xv.x - qx, qx);
        qy = fmaf(a.y, xv.y - qy, qy);
        qz = fmaf(a.z, xv.z - qz, qz);
        qw = fmaf(a.w, xv.w - qw, qw);
    }
    g_b[s * CG + cg] = make_float4(qx, qy, qz, qw);
}

// ---------------------------------------------------------------------------
// Warp-parallel first-order scan over segments.
// One warp = one scalar chain; lane = segment index.
// h_{s+1} = P * h_s + forcing_s,  P = (1-alpha)^L_SEG (constant per chain).
// Writes the EXCLUSIVE boundary (state at start of each segment).
// ---------------------------------------------------------------------------
__global__ void k_scan(const float* __restrict__ forcing,  // [SEG][NCHAIN]
                       const float* __restrict__ init,     // [NCHAIN]
                       const float* __restrict__ alpha,    // [NCHAIN]
                       float* __restrict__ bound,          // [SEG][NCHAIN]
                       int square_init) {
    int warp = (blockIdx.x * blockDim.x + threadIdx.x) >> 5;   // chain c
    int lane = threadIdx.x & 31;                               // segment s
    int c = warp;

    float a  = alpha[c];
    float P  = 1.f - a;
    #pragma unroll
    for (int k = 0; k < 7; k++) P *= P;       // (1-a)^128

    float A = forcing[lane * NCHAIN + c];

    // Kogge-Stone scan: A_s = sum_{j<=s} P^{s-j} b_j
    float pw = P;
    float pws0 = pw;
    { float t = __shfl_up_sync(0xFFFFFFFFu, A, 1);  if (lane >= 1)  A = fmaf(pw, t, A); pw *= pw; }
    float pws1 = pw;
    { float t = __shfl_up_sync(0xFFFFFFFFu, A, 2);  if (lane >= 2)  A = fmaf(pw, t, A); pw *= pw; }
    float pws2 = pw;
    { float t = __shfl_up_sync(0xFFFFFFFFu, A, 4);  if (lane >= 4)  A = fmaf(pw, t, A); pw *= pw; }
    float pws3 = pw;
    { float t = __shfl_up_sync(0xFFFFFFFFu, A, 8);  if (lane >= 8)  A = fmaf(pw, t, A); pw *= pw; }
    float pws4 = pw;
    { float t = __shfl_up_sync(0xFFFFFFFFu, A, 16); if (lane >= 16) A = fmaf(pw, t, A); }

    // exclusive shift
    float excl = __shfl_up_sync(0xFFFFFFFFu, A, 1);
    if (lane == 0) excl = 0.f;

    // P^lane via binary expansion of lane with captured squares
    float Pl = 1.f;
    if (lane & 1)  Pl *= pws0;
    if (lane & 2)  Pl *= pws1;
    if (lane & 4)  Pl *= pws2;
    if (lane & 8)  Pl *= pws3;
    if (lane & 16) Pl *= pws4;

    float h0 = init[c];
    if (square_init) h0 *= h0;

    bound[lane * NCHAIN + c] = fmaf(Pl, h0, excl);
}

// ---------------------------------------------------------------------------
// K3: replay ha from true boundary, write out_a, accumulate hv forcing f
// ---------------------------------------------------------------------------
__global__ void k_a(const float4* __restrict__ x4, const float4* __restrict__ a4p,
                    float4* __restrict__ out4) {
    int tid = blockIdx.x * blockDim.x + threadIdx.x;
    int s  = tid >> 11;
    int cg = tid & (CG - 1);
    int n  = cg >> 7;
    int g  = cg & (DQ - 1);

    float4 a = a4p[cg];
    float omx = 1.f - a.x, omy = 1.f - a.y, omz = 1.f - a.z, omw = 1.f - a.w;

    float4 ha = g_hab[s * CG + cg];
    float fx = 0.f, fy = 0.f, fz = 0.f, fw = 0.f;
    int t0 = s * L_SEG;

    #pragma unroll 4
    for (int i = 0; i < L_SEG; i++) {
        int t = t0 + i;
        float4 xv = x4[(size_t)t * DQ + g];
        float ux = xv.x - ha.x, uy = xv.y - ha.y, uz = xv.z - ha.z, uw = xv.w - ha.w;
        fx = omx * fmaf(a.x, ux * ux, fx);
        fy = omy * fmaf(a.y, uy * uy, fy);
        fz = omz * fmaf(a.z, uz * uz, fz);
        fw = omw * fmaf(a.w, uw * uw, fw);
        ha.x = fmaf(a.x, ux, ha.x);
        ha.y = fmaf(a.y, uy, ha.y);
        ha.z = fmaf(a.z, uz, ha.z);
        ha.w = fmaf(a.w, uw, ha.w);
        out4[((size_t)t * TWO_N + n) * DQ + g] = ha;
    }
    g_f[s * CG + cg] = make_float4(fx, fy, fz, fw);
}

// ---------------------------------------------------------------------------
// K5: full replay from true boundaries, write out_s (+ final states)
// ---------------------------------------------------------------------------
__global__ void k_s(const float4* __restrict__ x4, const float4* __restrict__ a4p,
                    float4* __restrict__ out4) {
    int tid = blockIdx.x * blockDim.x + threadIdx.x;
    int s  = tid >> 11;
    int cg = tid & (CG - 1);
    int n  = cg >> 7;
    int g  = cg & (DQ - 1);

    float4 a = a4p[cg];
    float omx = 1.f - a.x, omy = 1.f - a.y, omz = 1.f - a.z, omw = 1.f - a.w;

    float4 ha = g_hab[s * CG + cg];
    float4 hv = g_hvb[s * CG + cg];
    int t0 = s * L_SEG;

    #pragma unroll 4
    for (int i = 0; i < L_SEG; i++) {
        int t = t0 + i;
        float4 xv = x4[(size_t)t * DQ + g];
        float ux = xv.x - ha.x, uy = xv.y - ha.y, uz = xv.z - ha.z, uw = xv.w - ha.w;
        hv.x = omx * fmaf(a.x, ux * ux, hv.x);
        hv.y = omy * fmaf(a.y, uy * uy, hv.y);
        hv.z = omz * fmaf(a.z, uz * uz, hv.z);
        hv.w = omw * fmaf(a.w, uw * uw, hv.w);
        ha.x = fmaf(a.x, ux, ha.x);
        ha.y = fmaf(a.y, uy, ha.y);
        ha.z = fmaf(a.z, uz, ha.z);
        ha.w = fmaf(a.w, uw, ha.w);
        out4[((size_t)t * TWO_N + N_DIM + n) * DQ + g] =
            make_float4(sqrt_approx(hv.x), sqrt_approx(hv.y),
                        sqrt_approx(hv.z), sqrt_approx(hv.w));
    }

    if (s == SEG - 1) {
        // Final states: ha_N [N,D] then sqrt(hv_N) [N,D], appended after out
        const size_t base = (size_t)T_LEN * TWO_N * DQ;   // in float4 units
        out4[base + cg] = ha;
        out4[base + CG + cg] =
            make_float4(sqrt_approx(hv.x), sqrt_approx(hv.y),
                        sqrt_approx(hv.z), sqrt_approx(hv.w));
    }
}

// ---------------------------------------------------------------------------
extern "C" void kernel_launch(void* const* d_in, const int* in_sizes, int n_in,
                              void* d_out, int out_size) {
    const float4* x4  = (const float4*)d_in[0];   // [T, D]
    const float*  ha0 = (const float*)d_in[1];    // [N, D]
    const float*  hs0 = (const float*)d_in[2];    // [N, D]
    const float*  al  = (const float*)d_in[3];    // [N, D]
    const float4* a4  = (const float4*)d_in[3];
    float4* out4 = (float4*)d_out;

    // Resolve device-global scratch as scalar views for the scan kernels.
    // (Device globals are directly addressable from device code; for host-side
    //  launches we just pass pointers obtained via the kernels' own symbols.)
    k_b <<<BIG_THREADS / 256, 256>>>(x4, a4);

    // scan kernels take raw pointers to the device globals via cudaGetSymbolAddress-free
    // trick: a tiny launch passing symbol addresses is not needed since __device__
    // globals can be referenced inside the kernels. Instead, k_scan below takes
    // pointers; fetch them once via static device-symbol lookup.
    static float* p_b   = nullptr;
    static float* p_f   = nullptr;
    static float* p_hab = nullptr;
    static float* p_hvb = nullptr;
    if (!p_b) {
        cudaGetSymbolAddress((void**)&p_b,   g_b);
        cudaGetSymbolAddress((void**)&p_f,   g_f);
        cudaGetSymbolAddress((void**)&p_hab, g_hab);
        cudaGetSymbolAddress((void**)&p_hvb, g_hvb);
    }

    // 8192 chains, one warp each -> 262144 threads
    k_scan<<<NCHAIN * 32 / 256, 256>>>(p_b, ha0, al, p_hab, 0);
    k_a   <<<BIG_THREADS / 256, 256>>>(x4, a4, out4);
    k_scan<<<NCHAIN * 32 / 256, 256>>>(p_f, hs0, al, p_hvb, 1);
    k_s   <<<BIG_THREADS / 256, 256>>>(x4, a4, out4);
}

// round 3
// speedup vs baseline: 1.4477x; 1.4477x over previous
#include <cuda_runtime.h>

// Problem constants
#define T_LEN   4096
#define D_DIM   512
#define N_DIM   16
#define TWO_N   32
#define DQ      128            // D/4 (float4 groups per row)
#define SEG     64             // number of segments
#define L_SEG   64             // steps per segment (SEG*L_SEG == T_LEN)
#define CG      2048           // chain groups = N*D/4
#define NCHAIN  8192           // scalar chains = N*D
#define BIG_THREADS (SEG*CG)   // 131072

// Scratch (device globals). Scalar view: [SEG][NCHAIN].
__device__ float4 g_b  [SEG*CG];   // ha forcing per (seg, chain)
__device__ float4 g_f  [SEG*CG];   // hv forcing per (seg, chain)
__device__ float4 g_hab[SEG*CG];   // ha boundary at segment start
__device__ float4 g_hvb[SEG*CG];   // hv boundary at segment start

__device__ __forceinline__ float sqrt_approx(float v) {
    float r;
    asm("sqrt.approx.f32 %0, %1;" : "=f"(r) : "f"(v));
    return r;
}

// ---------------------------------------------------------------------------
// K1: zero-state ha replay per segment -> forcing term b
// ---------------------------------------------------------------------------
__global__ void k_b(const float4* __restrict__ x4, const float4* __restrict__ a4p) {
    int tid = blockIdx.x * blockDim.x + threadIdx.x;
    int s  = tid >> 11;          // segment
    int cg = tid & (CG - 1);     // chain group (n*128 + g)
    int g  = cg & (DQ - 1);

    float4 a = a4p[cg];
    float qx = 0.f, qy = 0.f, qz = 0.f, qw = 0.f;
    const float4* xp = x4 + (size_t)(s * L_SEG) * DQ + g;

    #pragma unroll 4
    for (int i = 0; i < L_SEG; i++) {
        float4 xv = xp[(size_t)i * DQ];
        qx = fmaf(a.x, xv.x - qx, qx);
        qy = fmaf(a.y, xv.y - qy, qy);
        qz = fmaf(a.z, xv.z - qz, qz);
        qw = fmaf(a.w, xv.w - qw, qw);
    }
    g_b[s * CG + cg] = make_float4(qx, qy, qz, qw);
}

// ---------------------------------------------------------------------------
// Warp-parallel first-order scan over 64 segments, 2 segments per lane.
// One warp = one scalar chain. h_{s+1} = P*h_s + b_s, P = (1-alpha)^L_SEG.
// Lane l owns segments 2l and 2l+1. Pair combine: coefficient Q = P^2,
// forcing C_l = P*b_{2l} + b_{2l+1}. KS-scan pairs, then reconstruct.
// Writes EXCLUSIVE boundaries (state at start of each segment).
// ---------------------------------------------------------------------------
__global__ void k_scan(const float* __restrict__ forcing,  // [SEG][NCHAIN]
                       const float* __restrict__ init,     // [NCHAIN]
                       const float* __restrict__ alpha,    // [NCHAIN]
                       float* __restrict__ bound,          // [SEG][NCHAIN]
                       int square_init) {
    int c    = (blockIdx.x * blockDim.x + threadIdx.x) >> 5;   // chain
    int lane = threadIdx.x & 31;                               // pair index

    float a = alpha[c];
    float P = 1.f - a;
    #pragma unroll
    for (int k = 0; k < 6; k++) P *= P;       // (1-a)^64

    float b0 = forcing[(2 * lane)     * NCHAIN + c];
    float b1 = forcing[(2 * lane + 1) * NCHAIN + c];
    float A  = fmaf(P, b0, b1);               // pair forcing
    float Q  = P * P;                         // pair coefficient

    // Kogge-Stone inclusive scan over pairs with coefficient Q
    float pw = Q;
    float q0 = pw;
    { float t = __shfl_up_sync(0xFFFFFFFFu, A, 1);  if (lane >= 1)  A = fmaf(pw, t, A); pw *= pw; }
    float q1 = pw;
    { float t = __shfl_up_sync(0xFFFFFFFFu, A, 2);  if (lane >= 2)  A = fmaf(pw, t, A); pw *= pw; }
    float q2 = pw;
    { float t = __shfl_up_sync(0xFFFFFFFFu, A, 4);  if (lane >= 4)  A = fmaf(pw, t, A); pw *= pw; }
    float q3 = pw;
    { float t = __shfl_up_sync(0xFFFFFFFFu, A, 8);  if (lane >= 8)  A = fmaf(pw, t, A); pw *= pw; }
    float q4 = pw;
    { float t = __shfl_up_sync(0xFFFFFFFFu, A, 16); if (lane >= 16) A = fmaf(pw, t, A); }

    // exclusive prefix at pair boundary
    float excl = __shfl_up_sync(0xFFFFFFFFu, A, 1);
    if (lane == 0) excl = 0.f;

    // Q^lane via binary expansion with captured squares
    float Ql = 1.f;
    if (lane & 1)  Ql *= q0;
    if (lane & 2)  Ql *= q1;
    if (lane & 4)  Ql *= q2;
    if (lane & 8)  Ql *= q3;
    if (lane & 16) Ql *= q4;

    float h0 = init[c];
    if (square_init) h0 *= h0;

    float bnd0 = fmaf(Ql, h0, excl);          // state at start of segment 2*lane
    float bnd1 = fmaf(P, bnd0, b0);           // state at start of segment 2*lane+1

    bound[(2 * lane)     * NCHAIN + c] = bnd0;
    bound[(2 * lane + 1) * NCHAIN + c] = bnd1;
}

// ---------------------------------------------------------------------------
// K3: replay ha from true boundary, write out_a, accumulate hv forcing f
// ---------------------------------------------------------------------------
__global__ void k_a(const float4* __restrict__ x4, const float4* __restrict__ a4p,
                    float4* __restrict__ out4) {
    int tid = blockIdx.x * blockDim.x + threadIdx.x;
    int s  = tid >> 11;
    int cg = tid & (CG - 1);
    int n  = cg >> 7;
    int g  = cg & (DQ - 1);

    float4 a = a4p[cg];
    float omx = 1.f - a.x, omy = 1.f - a.y, omz = 1.f - a.z, omw = 1.f - a.w;

    float4 ha = g_hab[s * CG + cg];
    float fx = 0.f, fy = 0.f, fz = 0.f, fw = 0.f;
    int t0 = s * L_SEG;

    #pragma unroll 4
    for (int i = 0; i < L_SEG; i++) {
        int t = t0 + i;
        float4 xv = x4[(size_t)t * DQ + g];
        float ux = xv.x - ha.x, uy = xv.y - ha.y, uz = xv.z - ha.z, uw = xv.w - ha.w;
        fx = omx * fmaf(a.x, ux * ux, fx);
        fy = omy * fmaf(a.y, uy * uy, fy);
        fz = omz * fmaf(a.z, uz * uz, fz);
        fw = omw * fmaf(a.w, uw * uw, fw);
        ha.x = fmaf(a.x, ux, ha.x);
        ha.y = fmaf(a.y, uy, ha.y);
        ha.z = fmaf(a.z, uz, ha.z);
        ha.w = fmaf(a.w, uw, ha.w);
        out4[((size_t)t * TWO_N + n) * DQ + g] = ha;
    }
    g_f[s * CG + cg] = make_float4(fx, fy, fz, fw);
}

// ---------------------------------------------------------------------------
// K5: full replay from true boundaries, write out_s (+ final states)
// ---------------------------------------------------------------------------
__global__ void k_s(const float4* __restrict__ x4, const float4* __restrict__ a4p,
                    float4* __restrict__ out4) {
    int tid = blockIdx.x * blockDim.x + threadIdx.x;
    int s  = tid >> 11;
    int cg = tid & (CG - 1);
    int n  = cg >> 7;
    int g  = cg & (DQ - 1);

    float4 a = a4p[cg];
    float omx = 1.f - a.x, omy = 1.f - a.y, omz = 1.f - a.z, omw = 1.f - a.w;

    float4 ha = g_hab[s * CG + cg];
    float4 hv = g_hvb[s * CG + cg];
    int t0 = s * L_SEG;

    #pragma unroll 4
    for (int i = 0; i < L_SEG; i++) {
        int t = t0 + i;
        float4 xv = x4[(size_t)t * DQ + g];
        float ux = xv.x - ha.x, uy = xv.y - ha.y, uz = xv.z - ha.z, uw = xv.w - ha.w;
        hv.x = omx * fmaf(a.x, ux * ux, hv.x);
        hv.y = omy * fmaf(a.y, uy * uy, hv.y);
        hv.z = omz * fmaf(a.z, uz * uz, hv.z);
        hv.w = omw * fmaf(a.w, uw * uw, hv.w);
        ha.x = fmaf(a.x, ux, ha.x);
        ha.y = fmaf(a.y, uy, ha.y);
        ha.z = fmaf(a.z, uz, ha.z);
        ha.w = fmaf(a.w, uw, ha.w);
        out4[((size_t)t * TWO_N + N_DIM + n) * DQ + g] =
            make_float4(sqrt_approx(hv.x), sqrt_approx(hv.y),
                        sqrt_approx(hv.z), sqrt_approx(hv.w));
    }

    if (s == SEG - 1) {
        // Final states: ha_N [N,D] then sqrt(hv_N) [N,D], appended after out
        const size_t base = (size_t)T_LEN * TWO_N * DQ;   // in float4 units
        out4[base + cg] = ha;
        out4[base + CG + cg] =
            make_float4(sqrt_approx(hv.x), sqrt_approx(hv.y),
                        sqrt_approx(hv.z), sqrt_approx(hv.w));
    }
}

// ---------------------------------------------------------------------------
extern "C" void kernel_launch(void* const* d_in, const int* in_sizes, int n_in,
                              void* d_out, int out_size) {
    const float4* x4  = (const float4*)d_in[0];   // [T, D]
    const float*  ha0 = (const float*)d_in[1];    // [N, D]
    const float*  hs0 = (const float*)d_in[2];    // [N, D]
    const float*  al  = (const float*)d_in[3];    // [N, D]
    const float4* a4  = (const float4*)d_in[3];
    float4* out4 = (float4*)d_out;

    static float* p_b   = nullptr;
    static float* p_f   = nullptr;
    static float* p_hab = nullptr;
    static float* p_hvb = nullptr;
    if (!p_b) {
        cudaGetSymbolAddress((void**)&p_b,   g_b);
        cudaGetSymbolAddress((void**)&p_f,   g_f);
        cudaGetSymbolAddress((void**)&p_hab, g_hab);
        cudaGetSymbolAddress((void**)&p_hvb, g_hvb);
    }

    k_b   <<<BIG_THREADS / 256, 256>>>(x4, a4);
    k_scan<<<NCHAIN * 32 / 256, 256>>>(p_b, ha0, al, p_hab, 0);
    k_a   <<<BIG_THREADS / 256, 256>>>(x4, a4, out4);
    k_scan<<<NCHAIN * 32 / 256, 256>>>(p_f, hs0, al, p_hvb, 1);
    k_s   <<<BIG_THREADS / 256, 256>>>(x4, a4, out4);
}

// round 4
// speedup vs baseline: 2.1715x; 1.5000x over previous
#include <cuda_runtime.h>

// Problem constants
#define T_LEN   4096
#define D_DIM   512
#define N_DIM   16
#define TWO_N   32
#define DQ      128            // D/4 (float4 groups per row)
#define SEG     64             // number of segments
#define L_SEG   64             // steps per segment (SEG*L_SEG == T_LEN)
#define CG      2048           // chain groups = N*D/4
#define BIG_THREADS (SEG*CG)   // 131072

// Scratch (device globals). Layout: [CG][SEG] float4 (chain-major, coalesced for scan).
__device__ float4 g_b  [CG*SEG];   // ha forcing
__device__ float4 g_f  [CG*SEG];   // hv forcing
__device__ float4 g_hab[CG*SEG];   // ha boundary at segment start
__device__ float4 g_hvb[CG*SEG];   // hv boundary at segment start

__device__ __forceinline__ float sqrt_approx(float v) {
    float r;
    asm("sqrt.approx.f32 %0, %1;" : "=f"(r) : "f"(v));
    return r;
}

// ---------------------------------------------------------------------------
// K1: zero-state ha replay per segment -> forcing term b.
// One thread handles 4 n-chains (same g, same x) to cut x re-reads 4x.
// Threads: SEG * DQ * 4 = 32768.
// ---------------------------------------------------------------------------
__global__ void k_b(const float4* __restrict__ x4, const float4* __restrict__ a4p) {
    int tid = blockIdx.x * blockDim.x + threadIdx.x;
    int s   = tid >> 9;            // segment (tid / 512)
    int r   = tid & 511;           // within segment
    int ng  = r >> 7;              // n-group 0..3 (covers n = ng*4 .. ng*4+3)
    int g   = r & (DQ - 1);

    float4 a0 = a4p[(ng * 4 + 0) * DQ + g];
    float4 a1 = a4p[(ng * 4 + 1) * DQ + g];
    float4 a2 = a4p[(ng * 4 + 2) * DQ + g];
    float4 a3 = a4p[(ng * 4 + 3) * DQ + g];

    float4 q0 = make_float4(0.f, 0.f, 0.f, 0.f);
    float4 q1 = q0, q2 = q0, q3 = q0;

    const float4* xp = x4 + (size_t)(s * L_SEG) * DQ + g;

    #pragma unroll 4
    for (int i = 0; i < L_SEG; i++) {
        float4 xv = xp[(size_t)i * DQ];
        q0.x = fmaf(a0.x, xv.x - q0.x, q0.x);
        q0.y = fmaf(a0.y, xv.y - q0.y, q0.y);
        q0.z = fmaf(a0.z, xv.z - q0.z, q0.z);
        q0.w = fmaf(a0.w, xv.w - q0.w, q0.w);
        q1.x = fmaf(a1.x, xv.x - q1.x, q1.x);
        q1.y = fmaf(a1.y, xv.y - q1.y, q1.y);
        q1.z = fmaf(a1.z, xv.z - q1.z, q1.z);
        q1.w = fmaf(a1.w, xv.w - q1.w, q1.w);
        q2.x = fmaf(a2.x, xv.x - q2.x, q2.x);
        q2.y = fmaf(a2.y, xv.y - q2.y, q2.y);
        q2.z = fmaf(a2.z, xv.z - q2.z, q2.z);
        q2.w = fmaf(a2.w, xv.w - q2.w, q2.w);
        q3.x = fmaf(a3.x, xv.x - q3.x, q3.x);
        q3.y = fmaf(a3.y, xv.y - q3.y, q3.y);
        q3.z = fmaf(a3.z, xv.z - q3.z, q3.z);
        q3.w = fmaf(a3.w, xv.w - q3.w, q3.w);
    }
    g_b[((ng * 4 + 0) * DQ + g) * SEG + s] = q0;
    g_b[((ng * 4 + 1) * DQ + g) * SEG + s] = q1;
    g_b[((ng * 4 + 2) * DQ + g) * SEG + s] = q2;
    g_b[((ng * 4 + 3) * DQ + g) * SEG + s] = q3;
}

// ---------------------------------------------------------------------------
// Warp-parallel first-order scan over 64 segments, 2 segments per lane.
// One warp = one float4 chain-group (4 scalar chains scanned in parallel).
// h_{s+1} = P*h_s + b_s,  P = (1-alpha)^L_SEG.  Lane l owns segs 2l, 2l+1.
// Loads/stores fully coalesced (scratch layout [CG][SEG]).
// ---------------------------------------------------------------------------
__global__ void k_scan(const float4* __restrict__ forcing,  // [CG][SEG]
                       const float4* __restrict__ init,     // [CG]
                       const float4* __restrict__ alpha,    // [CG]
                       float4* __restrict__ bound,          // [CG][SEG]
                       int square_init) {
    int cg   = (blockIdx.x * blockDim.x + threadIdx.x) >> 5;
    int lane = threadIdx.x & 31;

    float4 av = alpha[cg];
    float P[4] = {1.f - av.x, 1.f - av.y, 1.f - av.z, 1.f - av.w};
    #pragma unroll
    for (int k = 0; k < 6; k++) {
        #pragma unroll
        for (int j = 0; j < 4; j++) P[j] *= P[j];   // (1-a)^64
    }

    float4 b0v = forcing[cg * SEG + 2 * lane];
    float4 b1v = forcing[cg * SEG + 2 * lane + 1];
    float b0[4] = {b0v.x, b0v.y, b0v.z, b0v.w};
    float b1[4] = {b1v.x, b1v.y, b1v.z, b1v.w};

    float A[4], pw[4], qs[5][4];
    #pragma unroll
    for (int j = 0; j < 4; j++) {
        A[j]  = fmaf(P[j], b0[j], b1[j]);   // pair forcing
        pw[j] = P[j] * P[j];                // pair coefficient Q
    }

    #pragma unroll
    for (int step = 0; step < 5; step++) {
        int off = 1 << step;
        float t[4];
        #pragma unroll
        for (int j = 0; j < 4; j++) {
            qs[step][j] = pw[j];
            t[j] = __shfl_up_sync(0xFFFFFFFFu, A[j], off);
        }
        if (lane >= off) {
            #pragma unroll
            for (int j = 0; j < 4; j++) A[j] = fmaf(pw[j], t[j], A[j]);
        }
        #pragma unroll
        for (int j = 0; j < 4; j++) pw[j] *= pw[j];
    }

    float excl[4];
    #pragma unroll
    for (int j = 0; j < 4; j++) {
        excl[j] = __shfl_up_sync(0xFFFFFFFFu, A[j], 1);
        if (lane == 0) excl[j] = 0.f;
    }

    // Q^lane via binary expansion with captured squares
    float Ql[4] = {1.f, 1.f, 1.f, 1.f};
    #pragma unroll
    for (int bit = 0; bit < 5; bit++) {
        if (lane & (1 << bit)) {
            #pragma unroll
            for (int j = 0; j < 4; j++) Ql[j] *= qs[bit][j];
        }
    }

    float4 h0v = init[cg];
    float h0[4] = {h0v.x, h0v.y, h0v.z, h0v.w};
    if (square_init) {
        #pragma unroll
        for (int j = 0; j < 4; j++) h0[j] *= h0[j];
    }

    float bnd0[4], bnd1[4];
    #pragma unroll
    for (int j = 0; j < 4; j++) {
        bnd0[j] = fmaf(Ql[j], h0[j], excl[j]);   // state at start of seg 2*lane
        bnd1[j] = fmaf(P[j], bnd0[j], b0[j]);    // state at start of seg 2*lane+1
    }

    bound[cg * SEG + 2 * lane]     = make_float4(bnd0[0], bnd0[1], bnd0[2], bnd0[3]);
    bound[cg * SEG + 2 * lane + 1] = make_float4(bnd1[0], bnd1[1], bnd1[2], bnd1[3]);
}

// ---------------------------------------------------------------------------
// K3: replay ha from true boundary, write out_a (streaming), accumulate hv forcing
// ---------------------------------------------------------------------------
__global__ void k_a(const float4* __restrict__ x4, const float4* __restrict__ a4p,
                    float4* __restrict__ out4) {
    int tid = blockIdx.x * blockDim.x + threadIdx.x;
    int s  = tid >> 11;
    int cg = tid & (CG - 1);
    int n  = cg >> 7;
    int g  = cg & (DQ - 1);

    float4 a = a4p[cg];
    float omx = 1.f - a.x, omy = 1.f - a.y, omz = 1.f - a.z, omw = 1.f - a.w;

    float4 ha = g_hab[cg * SEG + s];
    float fx = 0.f, fy = 0.f, fz = 0.f, fw = 0.f;
    int t0 = s * L_SEG;

    #pragma unroll 4
    for (int i = 0; i < L_SEG; i++) {
        int t = t0 + i;
        float4 xv = x4[(size_t)t * DQ + g];
        float ux = xv.x - ha.x, uy = xv.y - ha.y, uz = xv.z - ha.z, uw = xv.w - ha.w;
        fx = omx * fmaf(a.x, ux * ux, fx);
        fy = omy * fmaf(a.y, uy * uy, fy);
        fz = omz * fmaf(a.z, uz * uz, fz);
        fw = omw * fmaf(a.w, uw * uw, fw);
        ha.x = fmaf(a.x, ux, ha.x);
        ha.y = fmaf(a.y, uy, ha.y);
        ha.z = fmaf(a.z, uz, ha.z);
        ha.w = fmaf(a.w, uw, ha.w);
        __stcs(&out4[((size_t)t * TWO_N + n) * DQ + g], ha);
    }
    g_f[cg * SEG + s] = make_float4(fx, fy, fz, fw);
}

// ---------------------------------------------------------------------------
// K5: full replay from true boundaries, write out_s (streaming, + final states)
// ---------------------------------------------------------------------------
__global__ void k_s(const float4* __restrict__ x4, const float4* __restrict__ a4p,
                    float4* __restrict__ out4) {
    int tid = blockIdx.x * blockDim.x + threadIdx.x;
    int s  = tid >> 11;
    int cg = tid & (CG - 1);
    int n  = cg >> 7;
    int g  = cg & (DQ - 1);

    float4 a = a4p[cg];
    float omx = 1.f - a.x, omy = 1.f - a.y, omz = 1.f - a.z, omw = 1.f - a.w;

    float4 ha = g_hab[cg * SEG + s];
    float4 hv = g_hvb[cg * SEG + s];
    int t0 = s * L_SEG;

    #pragma unroll 4
    for (int i = 0; i < L_SEG; i++) {
        int t = t0 + i;
        float4 xv = x4[(size_t)t * DQ + g];
        float ux = xv.x - ha.x, uy = xv.y - ha.y, uz = xv.z - ha.z, uw = xv.w - ha.w;
        hv.x = omx * fmaf(a.x, ux * ux, hv.x);
        hv.y = omy * fmaf(a.y, uy * uy, hv.y);
        hv.z = omz * fmaf(a.z, uz * uz, hv.z);
        hv.w = omw * fmaf(a.w, uw * uw, hv.w);
        ha.x = fmaf(a.x, ux, ha.x);
        ha.y = fmaf(a.y, uy, ha.y);
        ha.z = fmaf(a.z, uz, ha.z);
        ha.w = fmaf(a.w, uw, ha.w);
        __stcs(&out4[((size_t)t * TWO_N + N_DIM + n) * DQ + g],
               make_float4(sqrt_approx(hv.x), sqrt_approx(hv.y),
                           sqrt_approx(hv.z), sqrt_approx(hv.w)));
    }

    if (s == SEG - 1) {
        // Final states: ha_N [N,D] then sqrt(hv_N) [N,D], appended after out
        const size_t base = (size_t)T_LEN * TWO_N * DQ;   // in float4 units
        out4[base + cg] = ha;
        out4[base + CG + cg] =
            make_float4(sqrt_approx(hv.x), sqrt_approx(hv.y),
                        sqrt_approx(hv.z), sqrt_approx(hv.w));
    }
}

// ---------------------------------------------------------------------------
extern "C" void kernel_launch(void* const* d_in, const int* in_sizes, int n_in,
                              void* d_out, int out_size) {
    const float4* x4  = (const float4*)d_in[0];   // [T, D]
    const float4* ha0 = (const float4*)d_in[1];   // [N, D]
    const float4* hs0 = (const float4*)d_in[2];   // [N, D]
    const float4* a4  = (const float4*)d_in[3];   // [N, D]
    float4* out4 = (float4*)d_out;

    static float4* p_b   = nullptr;
    static float4* p_f   = nullptr;
    static float4* p_hab = nullptr;
    static float4* p_hvb = nullptr;
    if (!p_b) {
        cudaGetSymbolAddress((void**)&p_b,   g_b);
        cudaGetSymbolAddress((void**)&p_f,   g_f);
        cudaGetSymbolAddress((void**)&p_hab, g_hab);
        cudaGetSymbolAddress((void**)&p_hvb, g_hvb);
    }

    k_b   <<<(SEG * DQ * 4) / 256, 256>>>(x4, a4);
    k_scan<<<(CG * 32) / 256, 256>>>(p_b, ha0, a4, p_hab, 0);
    k_a   <<<BIG_THREADS / 256, 256>>>(x4, a4, out4);
    k_scan<<<(CG * 32) / 256, 256>>>(p_f, hs0, a4, p_hvb, 1);
    k_s   <<<BIG_THREADS / 256, 256>>>(x4, a4, out4);
}